// round 11
// baseline (speedup 1.0000x reference)
#include <cuda_runtime.h>

// TpsGridGen: theta (64, 50) -> grid (64, 256, 192, 2) fp32
// R11: P=3 warp-strided pixels/thread (best LDS ratio, from R10) +
//   - compile-time gx/gy linspace tables (no runtime fp64)
//   - ln2 folded into RBF coefs (U = d2*lg2(d2), one MUFU per entry)
//   - 16 batches/block x 4 quarters -> 2048 warps, bounds(128,3)

#define OUT_H 256
#define OUT_W 192
#define NCP   25
#define NCOEF 28   // 25 RBF + [1, gx, gy] affine
#define NBQ   16   // batches per block

__host__ __device__ constexpr float cpx(int n) { return 0.5f * (float)(n / 5) - 1.0f; }
__host__ __device__ constexpr float cpy(int n) { return 0.5f * (float)(n % 5) - 1.0f; }

// ---------------------------------------------------------------------------
// Compile-time inv(L) (constexpr fp64 Gauss-Jordan w/ pivoting + constexpr log)
// ---------------------------------------------------------------------------
struct TPSConst { float li[NCOEF][NCP]; };

constexpr double cfabs(double x) { return x < 0.0 ? -x : x; }

constexpr double clog(double x) {
    int e = 0;
    while (x >= 1.4142135623730951) { x *= 0.5; e++; }
    while (x <  0.7071067811865476) { x *= 2.0; e--; }
    double t = (x - 1.0) / (x + 1.0), t2 = t * t, p = t, s = 0.0;
    for (int k = 0; k < 27; k++) { s += p / (double)(2 * k + 1); p *= t2; }
    return 2.0 * s + (double)e * 0.6931471805599453094172321214581766;
}

constexpr TPSConst make_tps() {
    TPSConst r{};
    const double ax[5] = {-1.0, -0.5, 0.0, 0.5, 1.0};
    double PX[NCP] = {}, PY[NCP] = {};
    for (int i = 0; i < 5; i++)
        for (int j = 0; j < 5; j++) { PX[i*5+j] = ax[i]; PY[i*5+j] = ax[j]; }

    double a[28][56] = {};
    for (int i = 0; i < 25; i++)
        for (int j = 0; j < 25; j++) {
            if (i != j) {
                double dx = PX[i]-PX[j], dy = PY[i]-PY[j];
                double d2 = dx*dx + dy*dy;
                a[i][j] = d2 * clog(d2);
            }
        }
    for (int i = 0; i < 25; i++) {
        a[i][25] = 1.0; a[i][26] = PX[i]; a[i][27] = PY[i];
        a[25][i] = 1.0; a[26][i] = PX[i]; a[27][i] = PY[i];
    }
    for (int i = 0; i < 28; i++) a[i][28+i] = 1.0;

    for (int k = 0; k < 28; k++) {
        int piv = k; double best = cfabs(a[k][k]);
        for (int i = k+1; i < 28; i++) {
            double v = cfabs(a[i][k]);
            if (v > best) { best = v; piv = i; }
        }
        if (piv != k)
            for (int j = 0; j < 56; j++) {
                double t = a[k][j]; a[k][j] = a[piv][j]; a[piv][j] = t;
            }
        double inv = 1.0 / a[k][k];
        for (int j = 0; j < 56; j++) a[k][j] *= inv;
        for (int i = 0; i < 28; i++) {
            if (i == k) continue;
            double f = a[i][k];
            if (f != 0.0)
                for (int j = 0; j < 56; j++) a[i][j] -= f * a[k][j];
        }
    }
    for (int n = 0; n < NCOEF; n++)
        for (int m = 0; m < NCP; m++)
            r.li[n][m] = (float)a[n][28 + m];
    return r;
}

// Transposed + lane-duplicated Li, RBF rows (coef<25) pre-scaled by ln2 so
// phase B can use lg2 instead of ln. v[m][part][j] = dup(scale * li[part*7+j][m]).
struct alignas(16) TPSLi2 { float2 v[NCP][4][8]; };

constexpr TPSLi2 make_li2() {
    TPSLi2 r{};
    TPSConst t = make_tps();
    const double LN2 = 0.6931471805599453094172321214581766;
    for (int m = 0; m < NCP; m++)
        for (int part = 0; part < 4; part++)
            for (int j = 0; j < 7; j++) {
                const int coef = part * 7 + j;
                double s = (coef < 25) ? LN2 : 1.0;
                float v = (float)(s * (double)t.li[coef][m]);
                r.v[m][part][j] = float2{v, v};
            }
    return r;
}

__device__ const TPSLi2 g_li2 = make_li2();

// Compile-time linspace tables (numpy fp64 semantics, endpoint exact).
struct alignas(16) GridTab { float g[448]; };   // [0..191]=gx, [192..447]=gy

constexpr GridTab make_grid() {
    GridTab r{};
    for (int w = 0; w < OUT_W; w++)
        r.g[w] = (float)(-1.0 + (double)w * (2.0 / (double)(OUT_W - 1)));
    r.g[OUT_W - 1] = 1.0f;
    for (int h = 0; h < OUT_H; h++)
        r.g[192 + h] = (float)(-1.0 + (double)h * (2.0 / (double)(OUT_H - 1)));
    r.g[192 + OUT_H - 1] = 1.0f;
    return r;
}

__device__ const GridTab g_grid = make_grid();

// ---------------------------------------------------------------------------
// Packed f32x2 helpers
// ---------------------------------------------------------------------------
__device__ __forceinline__ unsigned long long pack2(float lo, float hi) {
    unsigned long long r;
    asm("mov.b64 %0, {%1, %2};" : "=l"(r) : "f"(lo), "f"(hi));
    return r;
}
__device__ __forceinline__ unsigned long long fma2(unsigned long long a,
                                                   unsigned long long b,
                                                   unsigned long long c) {
    unsigned long long d;
    asm("fma.rn.f32x2 %0, %1, %2, %3;" : "=l"(d) : "l"(a), "l"(b), "l"(c));
    return d;
}

// ---------------------------------------------------------------------------
// Fused kernel. grid (128, 4), block 128, 3 blocks/SM.
// Thread: 3 warp-strided pixels x 16 batches.
// ---------------------------------------------------------------------------
__global__ __launch_bounds__(128, 3) void tps_fused_kernel(
    const float* __restrict__ theta, float2* __restrict__ out) {

    __shared__ __align__(16) float  s_theta[NBQ * 2 * NCP];  // 3.2 KB
    __shared__ __align__(16) float2 s_li[NCP * 4 * 8];       // 6.4 KB
    __shared__ __align__(16) float  s_grid[448];             // 1.8 KB
    __shared__ __align__(16) float2 s_coef[NBQ * NCOEF];     // 3.5 KB

    const int tid   = threadIdx.x;
    const int wid   = tid >> 5;
    const int lid   = tid & 31;
    const int qtr   = blockIdx.y;
    const int bbase = qtr * NBQ;

    // ---- Stage theta / Li / grid tables (coalesced float4) ----
    {
        const float4* tsrc = (const float4*)(theta + bbase * 2 * NCP);
        const float4* lsrc = (const float4*)&g_li2;
        const float4* gsrc = (const float4*)&g_grid;
        float4* tdst = (float4*)s_theta;
        float4* ldst = (float4*)s_li;
        float4* gdst = (float4*)s_grid;
        for (int i = tid; i < 200; i += 128) tdst[i] = tsrc[i];
        for (int i = tid; i < 400; i += 128) ldst[i] = lsrc[i];
        for (int i = tid; i < 112; i += 128) gdst[i] = gsrc[i];
    }
    __syncthreads();

    // ---- Phase A: coef solve (64 threads: batch x coef-quarter) ----
    if (tid < 64) {
        const int b    = tid & 15;
        const int part = tid >> 4;
        unsigned long long acc[7];
#pragma unroll
        for (int j = 0; j < 7; j++) acc[j] = 0ull;
        const float* trow = s_theta + b * (2 * NCP);
#pragma unroll
        for (int m = 0; m < NCP; m++) {
            const unsigned long long q2 =
                pack2(trow[m] + cpx(m), trow[NCP + m] + cpy(m));
            const unsigned long long* lrow =
                (const unsigned long long*)(s_li + (m * 4 + part) * 8);
#pragma unroll
            for (int j = 0; j < 7; j++)
                acc[j] = fma2(lrow[j], q2, acc[j]);
        }
        unsigned long long* dst =
            (unsigned long long*)(s_coef + b * NCOEF + part * 7);
#pragma unroll
        for (int j = 0; j < 7; j++) dst[j] = acc[j];
    }

    // ---- U for 3 warp-strided pixels; u = d2 * lg2(d2) (ln2 in coefs) ----
    const int wbase = blockIdx.x * 384 + wid * 96;
    const int px0 = wbase + lid;
    const int h  = px0 / OUT_W;
    const int w0 = px0 - h * OUT_W;

    const float gy  = s_grid[192 + h];
    const float gx0 = s_grid[w0];
    const float gx1 = s_grid[w0 + 32];
    const float gx2 = s_grid[w0 + 64];

    unsigned long long U0[NCOEF], U1[NCOEF], U2[NCOEF];
#pragma unroll
    for (int n = 0; n < NCP; n++) {
        const float dy  = gy - cpy(n);
        const float dy2 = dy * dy;
        const float dx0 = gx0 - cpx(n);
        const float dx1 = gx1 - cpx(n);
        const float dx2 = gx2 - cpx(n);
        const float d20 = dx0 * dx0 + dy2;
        const float d21 = dx1 * dx1 + dy2;
        const float d22 = dx2 * dx2 + dy2;
        const float u0 = (d20 == 0.0f) ? 0.0f : d20 * __log2f(d20);
        const float u1 = (d21 == 0.0f) ? 0.0f : d21 * __log2f(d21);
        const float u2 = (d22 == 0.0f) ? 0.0f : d22 * __log2f(d22);
        U0[n] = pack2(u0, u0);
        U1[n] = pack2(u1, u1);
        U2[n] = pack2(u2, u2);
    }
    U0[25] = pack2(1.0f, 1.0f);  U1[25] = U0[25];          U2[25] = U0[25];
    U0[26] = pack2(gx0, gx0);    U1[26] = pack2(gx1, gx1); U2[26] = pack2(gx2, gx2);
    U0[27] = pack2(gy, gy);      U1[27] = U0[27];          U2[27] = U0[27];

    __syncthreads();   // coefs visible

    // ---- Phase B: 16 batches, 2 per iter; 6 chains; 1 LDS.128 : 6 FMA2 ----
    char* obase = (char*)out + ((size_t)(bbase * OUT_H) * OUT_W + px0) * 8;
    const size_t ostride = (size_t)OUT_H * OUT_W * 8;
    for (int bl = 0; bl < NBQ; bl += 2) {
        const ulonglong2* c0 = (const ulonglong2*)(s_coef + (bl)     * NCOEF);
        const ulonglong2* c1 = (const ulonglong2*)(s_coef + (bl + 1) * NCOEF);
        unsigned long long a00 = 0ull, a01 = 0ull, a02 = 0ull;
        unsigned long long a10 = 0ull, a11 = 0ull, a12 = 0ull;
#pragma unroll
        for (int q = 0; q < NCOEF / 2; q++) {
            const ulonglong2 p0 = c0[q];
            const ulonglong2 p1 = c1[q];
            a00 = fma2(U0[2*q], p0.x, a00); a00 = fma2(U0[2*q+1], p0.y, a00);
            a01 = fma2(U1[2*q], p0.x, a01); a01 = fma2(U1[2*q+1], p0.y, a01);
            a02 = fma2(U2[2*q], p0.x, a02); a02 = fma2(U2[2*q+1], p0.y, a02);
            a10 = fma2(U0[2*q], p1.x, a10); a10 = fma2(U0[2*q+1], p1.y, a10);
            a11 = fma2(U1[2*q], p1.x, a11); a11 = fma2(U1[2*q+1], p1.y, a11);
            a12 = fma2(U2[2*q], p1.x, a12); a12 = fma2(U2[2*q+1], p1.y, a12);
        }
        *(unsigned long long*)(obase)                 = a00;
        *(unsigned long long*)(obase + 256)           = a01;
        *(unsigned long long*)(obase + 512)           = a02;
        *(unsigned long long*)(obase + ostride)       = a10;
        *(unsigned long long*)(obase + ostride + 256) = a11;
        *(unsigned long long*)(obase + ostride + 512) = a12;
        obase += 2 * ostride;
    }
}

// ---------------------------------------------------------------------------
extern "C" void kernel_launch(void* const* d_in, const int* in_sizes, int n_in,
                              void* d_out, int out_size) {
    const float* theta = (const float*)d_in[0];
    (void)in_sizes; (void)n_in; (void)out_size;

    dim3 grid(OUT_H * OUT_W / 384, 4);   // (128, 4)
    tps_fused_kernel<<<grid, 128>>>(theta, (float2*)d_out);
}